// round 9
// baseline (speedup 1.0000x reference)
#include <cuda_runtime.h>
#include <cuda_fp16.h>
#include <cuda_bf16.h>
#include <float.h>
#include <stdint.h>

// ============================ problem constants ============================
#define BATCH   4096
#define NVIEW   20
#define CDIM    512
#define HID     256
#define NCLS    40
#define SEL     8

#define VROWS   (BATCH * NVIEW)        // 81920
#define NPOOLCTA 32
#define NVIEWCTA 640
#define NCTA     (NPOOLCTA + NVIEWCTA) // 672

#define FNEW_OFF   0
#define FNEW_CNT   (BATCH * SEL * CDIM)
#define SCORE_OFF  FNEW_CNT
#define SCORE_CNT  (BATCH * NVIEW * NCLS)
#define VNEW_OFF   (SCORE_OFF + SCORE_CNT)

// ============================ mma.sync GEMM config =========================
// fp16 m16n8k16, 2-way split, 3 passes. Global scaling X*16, W*256 (epilogue /4096).
#define BMT       128
#define KCHUNK    32
#define NCHUNKS   (CDIM / KCHUNK)      // 16
#define A_PAD     40
#define XSCALE    16.0f
#define WSCALE    256.0f
#define INVSCALE  (1.0f / 4096.0f)

// smem byte offsets
#define OFF_A0    0
#define A_STAGE   (BMT * A_PAD * 4)    // 20480
#define OFF_A1    A_STAGE
#define OFF_B0    (2 * A_STAGE)        // 40960
#define B_STAGE   32768
#define OFF_B1    (OFF_B0 + B_STAGE)   // 73728  (+B_STAGE = 106496)
#define H_STRIDE  260
#define OFF_H     0
#define OFF_W2    (BMT * H_STRIDE * 4)            // 133120 (disjoint from mainloop region)
#define SMEM_BYTES (OFF_W2 + NCLS * H_STRIDE * 4) // 174720

// ============================ device scratch ===============================
__device__ float    g_pooled[BATCH * CDIM];
__device__ int      g_pred[BATCH];
// W1^T fp16 hi/lo quads: [ks16][n][kk] x 16B; quad = {b0hi, b1hi, b0lo, b1lo}
__device__ uint32_t g_w1p[32 * 256 * 4 * 4];   // 512 KB

typedef unsigned long long u64;

// ============================ helpers ======================================
__device__ __forceinline__ uint32_t smem_u32(const void* p) {
    uint32_t a;
    asm("{ .reg .u64 t; cvta.to.shared.u64 t, %1; cvt.u32.u64 %0, t; }" : "=r"(a) : "l"(p));
    return a;
}
__device__ __forceinline__ void mma_f16(float* d, const uint32_t* a, uint32_t b0, uint32_t b1) {
    asm volatile(
        "mma.sync.aligned.m16n8k16.row.col.f32.f16.f16.f32 "
        "{%0,%1,%2,%3}, {%4,%5,%6,%7}, {%8,%9}, {%0,%1,%2,%3};"
        : "+f"(d[0]), "+f"(d[1]), "+f"(d[2]), "+f"(d[3])
        : "r"(a[0]), "r"(a[1]), "r"(a[2]), "r"(a[3]), "r"(b0), "r"(b1));
}
// packed fp32 FMA: two IEEE fp32 FMAs per issue (Blackwell f32x2 pipe)
__device__ __forceinline__ void fma2(u64& d, u64 a, u64 b) {
    asm("fma.rn.f32x2 %0, %1, %2, %0;" : "+l"(d) : "l"(a), "l"(b));
}
__device__ __forceinline__ void cpasync16(uint32_t dst, const void* src) {
    asm volatile("cp.async.cg.shared.global [%0], [%1], 16;" :: "r"(dst), "l"(src));
}
#define CP_COMMIT()  asm volatile("cp.async.commit_group;" ::: "memory")
#define CP_WAIT(N)   asm volatile("cp.async.wait_group %0;" :: "n"(N) : "memory")

__device__ __forceinline__ void pack_split(float2 v, uint32_t& hi, uint32_t& lo) {
    float x0 = v.x * XSCALE, x1 = v.y * XSCALE;
    __half h0 = __float2half_rn(x0), h1 = __float2half_rn(x1);
    __half2 hp = __halves2half2(h0, h1);
    hi = *reinterpret_cast<uint32_t*>(&hp);
    float r0 = x0 - __half2float(h0), r1 = x1 - __half2float(h1);
    __half2 lp = __halves2half2(__float2half_rn(r0), __float2half_rn(r1));
    lo = *reinterpret_cast<uint32_t*>(&lp);
}

// ---------------------------------------------------------------------------
// Kernel P: split W1*256 into fp16 hi/lo quads in the streaming layout
// ---------------------------------------------------------------------------
__global__ void prep_w1_kernel(const float* __restrict__ W1) {
    int i = blockIdx.x * blockDim.x + threadIdx.x;
    int k = i >> 8;
    int n = i & 255;
    float w = W1[i] * WSCALE;
    __half hi = __float2half_rn(w);
    float r = w - __half2float(hi);
    __half lo = __float2half_rn(r);
    int ks   = k >> 4;
    int kpos = k & 15;
    int kk   = (kpos & 7) >> 1;
    int breg = kpos >> 3;
    int hsel = kpos & 1;
    uint16_t* q = reinterpret_cast<uint16_t*>(g_w1p) + ((size_t)(ks * 256 + n) * 4 + kk) * 8;
    q[breg * 2 + hsel]     = *reinterpret_cast<uint16_t*>(&hi);
    q[4 + breg * 2 + hsel] = *reinterpret_cast<uint16_t*>(&lo);
}

// ---------------------------------------------------------------------------
// Kernel B: 3-pass fp16 mma.sync MLP, fused pooling, f32x2 GEMM2.
// ---------------------------------------------------------------------------
__global__ __launch_bounds__(256, 1)
void mlp_mma_kernel(const float* __restrict__ F0,
                    const float* __restrict__ bias1,
                    const float* __restrict__ W2,
                    const float* __restrict__ bias2,
                    float* __restrict__ score_out) {
    extern __shared__ char smem[];
    const uint32_t sb = smem_u32(smem);
    const int t   = threadIdx.x;
    const int wid = t >> 5;
    const int l   = t & 31;
    const int wr  = wid >> 1;
    const int wc  = wid & 1;

    const bool pooled = (blockIdx.x < NPOOLCTA);
    const float* Xbase;
    int blockRow = 0;

    // ---- stage W2^T early: OFF_W2 region is disjoint from mainloop stages ----
    float* sW2 = (float*)(smem + OFF_W2);
    for (int idx = t; idx < HID * NCLS; idx += 256) {
        int k = idx / NCLS, cc = idx - k * NCLS;
        sW2[cc * H_STRIDE + k] = W2[idx];
    }

    if (pooled) {
        // phase 0: pool this CTA's 128 batches (self-produced -> race-free)
        const int b0 = blockIdx.x * BMT;
        float4* dstP = reinterpret_cast<float4*>(g_pooled) + (size_t)b0 * 128;
        const float4* srcP = reinterpret_cast<const float4*>(F0) + (size_t)b0 * (NVIEW * 128);
        const float inv = 1.0f / 20.0f;
        for (int i = t; i < BMT * 128; i += 256) {
            int bb = i >> 7, c4 = i & 127;
            const float4* p = srcP + (size_t)bb * (NVIEW * 128) + c4;
            float4 s = p[0];
#pragma unroll
            for (int n = 1; n < NVIEW; n++) {
                float4 q = p[n * 128];
                s.x += q.x; s.y += q.y; s.z += q.z; s.w += q.w;
            }
            s.x *= inv; s.y *= inv; s.z *= inv; s.w *= inv;
            dstP[i] = s;
        }
        __syncthreads();
        Xbase = g_pooled + (size_t)b0 * CDIM;
    } else {
        blockRow = (blockIdx.x - NPOOLCTA) * BMT;
        Xbase = F0 + (size_t)blockRow * CDIM;
    }

    // ---- accumulators ----
    float acc[2][16][4];
#pragma unroll
    for (int nt = 0; nt < 16; nt++)
#pragma unroll
        for (int mt = 0; mt < 2; mt++) {
            acc[mt][nt][0] = 0.f; acc[mt][nt][1] = 0.f;
            acc[mt][nt][2] = 0.f; acc[mt][nt][3] = 0.f;
        }

    auto load_chunk = [&](int stage, int c) {
        uint32_t dA = sb + (stage ? OFF_A1 : OFF_A0);
        uint32_t dB = sb + (stage ? OFF_B1 : OFF_B0);
#pragma unroll
        for (int j = 0; j < 4; j++) {
            int o = t + j * 256;
            int row = o >> 3, seg = o & 7;
            cpasync16(dA + row * (A_PAD * 4) + seg * 16,
                      (const char*)Xbase + (size_t)row * (CDIM * 4) + c * (KCHUNK * 4) + seg * 16);
        }
        const char* srcB = (const char*)g_w1p + (size_t)c * B_STAGE;
#pragma unroll
        for (int j = 0; j < 8; j++) {
            int off = (t + j * 256) * 16;
            cpasync16(dB + off, srcB + off);
        }
    };

    load_chunk(0, 0);
    CP_COMMIT();

#pragma unroll 1
    for (int c = 0; c < NCHUNKS; c++) {
        if (c < NCHUNKS - 1) {
            load_chunk((c + 1) & 1, c + 1);
            CP_COMMIT();
            CP_WAIT(1);
        } else {
            CP_WAIT(0);
        }
        __syncthreads();

        const float* Asm = (const float*)(smem + ((c & 1) ? OFF_A1 : OFF_A0));
        const char*  Bsm = smem + ((c & 1) ? OFF_B1 : OFF_B0);

#pragma unroll
        for (int s = 0; s < 2; s++) {
            uint32_t aHi[2][4], aLo[2][4];
#pragma unroll
            for (int mt = 0; mt < 2; mt++) {
                int r0 = wr * 32 + mt * 16 + (l >> 2);
                int c0 = s * 16 + 2 * (l & 3);
                const float* Ar  = Asm + r0 * A_PAD;
                const float* Ar8 = Asm + (r0 + 8) * A_PAD;
                pack_split(*(const float2*)&Ar[c0],      aHi[mt][0], aLo[mt][0]);
                pack_split(*(const float2*)&Ar8[c0],     aHi[mt][1], aLo[mt][1]);
                pack_split(*(const float2*)&Ar[c0 + 8],  aHi[mt][2], aLo[mt][2]);
                pack_split(*(const float2*)&Ar8[c0 + 8], aHi[mt][3], aLo[mt][3]);
            }
#pragma unroll
            for (int nt = 0; nt < 16; nt++) {
                uint4 q = *(const uint4*)(Bsm + s * 16384 + (wc * 512 + nt * 32 + l) * 16);
#pragma unroll
                for (int mt = 0; mt < 2; mt++) {
                    mma_f16(acc[mt][nt], aHi[mt], q.z, q.w);   // hiA * loB
                    mma_f16(acc[mt][nt], aLo[mt], q.x, q.y);   // loA * hiB
                    mma_f16(acc[mt][nt], aHi[mt], q.x, q.y);   // hiA * hiB
                }
            }
        }
        __syncthreads();
    }

    // ---- epilogue: unscale + bias + LeakyReLU -> H smem ----
    float* Hf = (float*)(smem + OFF_H);
#pragma unroll
    for (int mt = 0; mt < 2; mt++) {
        int r0 = wr * 32 + mt * 16 + (l >> 2);
#pragma unroll
        for (int nt = 0; nt < 16; nt++) {
            int n0 = wc * 128 + nt * 8 + 2 * (l & 3);
            float b0v = bias1[n0], b1v = bias1[n0 + 1];
            float2 p; float v;
            v = acc[mt][nt][0] * INVSCALE + b0v; p.x = v > 0.f ? v : 0.2f * v;
            v = acc[mt][nt][1] * INVSCALE + b1v; p.y = v > 0.f ? v : 0.2f * v;
            *(float2*)&Hf[r0 * H_STRIDE + n0] = p;
            v = acc[mt][nt][2] * INVSCALE + b0v; p.x = v > 0.f ? v : 0.2f * v;
            v = acc[mt][nt][3] * INVSCALE + b1v; p.y = v > 0.f ? v : 0.2f * v;
            *(float2*)&Hf[(r0 + 8) * H_STRIDE + n0] = p;
        }
    }
    __syncthreads();

    // ---- GEMM2 via packed f32x2: 128x40 = H[128][256] @ W2 ----
    const int rg = t >> 3;
    const int cg = t & 7;
    u64 s2p[4][5];
#pragma unroll
    for (int j = 0; j < 5; j++) {
        float2 init = make_float2(bias2[cg * 5 + j], 0.f);
        u64 iv = *reinterpret_cast<u64*>(&init);
        s2p[0][j] = iv; s2p[1][j] = iv; s2p[2][j] = iv; s2p[3][j] = iv;
    }
#pragma unroll 4
    for (int k = 0; k < HID; k += 4) {
        ulonglong2 h0 = *(const ulonglong2*)(Hf + (rg * 4 + 0) * H_STRIDE + k);
        ulonglong2 h1 = *(const ulonglong2*)(Hf + (rg * 4 + 1) * H_STRIDE + k);
        ulonglong2 h2 = *(const ulonglong2*)(Hf + (rg * 4 + 2) * H_STRIDE + k);
        ulonglong2 h3 = *(const ulonglong2*)(Hf + (rg * 4 + 3) * H_STRIDE + k);
#pragma unroll
        for (int j = 0; j < 5; j++) {
            ulonglong2 w = *(const ulonglong2*)(sW2 + (cg * 5 + j) * H_STRIDE + k);
            fma2(s2p[0][j], h0.x, w.x); fma2(s2p[0][j], h0.y, w.y);
            fma2(s2p[1][j], h1.x, w.x); fma2(s2p[1][j], h1.y, w.y);
            fma2(s2p[2][j], h2.x, w.x); fma2(s2p[2][j], h2.y, w.y);
            fma2(s2p[3][j], h3.x, w.x); fma2(s2p[3][j], h3.y, w.y);
        }
    }
    __syncthreads();

    // stage score tile [128][40] flat (sum packed halves)
#pragma unroll
    for (int rr = 0; rr < 4; rr++)
#pragma unroll
        for (int j = 0; j < 5; j++) {
            float2 p = *reinterpret_cast<float2*>(&s2p[rr][j]);
            Hf[(rg * 4 + rr) * NCLS + cg * 5 + j] = p.x + p.y;
        }
    __syncthreads();

    if (!pooled) {
        float* dst = score_out + (size_t)blockRow * NCLS;
        for (int idx = t; idx < BMT * NCLS; idx += 256)
            dst[idx] = Hf[idx];
    } else if (t < BMT) {
        const float* row = &Hf[t * NCLS];
        float best = row[0]; int bi = 0;
#pragma unroll
        for (int i = 1; i < NCLS; i++)
            if (row[i] > best) { best = row[i]; bi = i; }   // first max (jnp.argmax)
        g_pred[blockIdx.x * BMT + t] = bi;
    }
}

// ---------------------------------------------------------------------------
// Kernel C: 8 batches/block; warp-topk + wide gather. [R7-proven]
// ---------------------------------------------------------------------------
__global__ __launch_bounds__(256)
void select_kernel(const float* __restrict__ F0,
                   const float* __restrict__ V0,
                   const float* __restrict__ score,
                   float* __restrict__ Fnew,
                   float* __restrict__ Vnew) {
    const int t = threadIdx.x;
    const int w = t >> 5;
    const int lane = t & 31;
    const int b = blockIdx.x * 8 + w;
    __shared__ int sidx[8][SEL];

    {
        int pred = g_pred[b];
        float v = (lane < NVIEW) ? score[((size_t)b * NVIEW + lane) * NCLS + pred] : -FLT_MAX;
        int myn = lane;
#pragma unroll
        for (int sstep = 0; sstep < SEL; sstep++) {
            float bv = v; int bi = myn;
#pragma unroll
            for (int off = 16; off > 0; off >>= 1) {
                float ov = __shfl_down_sync(0xffffffffu, bv, off);
                int   oi = __shfl_down_sync(0xffffffffu, bi, off);
                if (ov > bv || (ov == bv && oi < bi)) { bv = ov; bi = oi; }
            }
            bi = __shfl_sync(0xffffffffu, bi, 0);
            if (lane == 0) sidx[w][sstep] = bi;
            if (myn == bi) v = -FLT_MAX;
        }
    }
    __syncthreads();

    const float4* Fsrc = reinterpret_cast<const float4*>(F0);
    float4* Fdst = reinterpret_cast<float4*>(Fnew);
#pragma unroll
    for (int j = 0; j < 32; j++) {
        int i = t + j * 256;
        int bl = i >> 10, srow = (i >> 7) & 7, c = i & 127;
        int bb = blockIdx.x * 8 + bl;
        Fdst[((size_t)bb * SEL + srow) * 128 + c] =
            Fsrc[((size_t)bb * NVIEW + sidx[bl][srow]) * 128 + c];
    }
    if (t < 8 * SEL * 3) {
        int bl = t / (SEL * 3), r = t % (SEL * 3);
        int srow = r / 3, cmp = r - srow * 3;
        int bb = blockIdx.x * 8 + bl;
        Vnew[(size_t)bb * (SEL * 3) + r] = V0[(size_t)bb * (NVIEW * 3) + sidx[bl][srow] * 3 + cmp];
    }
}

// ---------------------------------------------------------------------------
extern "C" void kernel_launch(void* const* d_in, const int* in_sizes, int n_in,
                              void* d_out, int out_size) {
    (void)in_sizes; (void)n_in; (void)out_size;
    const float* F0 = (const float*)d_in[0];
    const float* V0 = (const float*)d_in[1];
    const float* W1 = (const float*)d_in[2];
    const float* b1 = (const float*)d_in[3];
    const float* W2 = (const float*)d_in[4];
    const float* b2 = (const float*)d_in[5];
    float* out   = (float*)d_out;
    float* Fnew  = out + FNEW_OFF;
    float* score = out + SCORE_OFF;
    float* Vnew  = out + VNEW_OFF;

    cudaFuncSetAttribute(mlp_mma_kernel, cudaFuncAttributeMaxDynamicSharedMemorySize, SMEM_BYTES);

    prep_w1_kernel<<<(CDIM * HID) / 256, 256>>>(W1);
    mlp_mma_kernel<<<NCTA, 256, SMEM_BYTES>>>(F0, b1, W2, b2, score);
    select_kernel<<<BATCH / 8, 256>>>(F0, V0, score, Fnew, Vnew);
}

// round 10
// speedup vs baseline: 1.7547x; 1.7547x over previous
#include <cuda_runtime.h>
#include <cuda_fp16.h>
#include <cuda_bf16.h>
#include <float.h>
#include <stdint.h>

// ============================ problem constants ============================
#define BATCH   4096
#define NVIEW   20
#define CDIM    512
#define HID     256
#define NCLS    40
#define SEL     8

#define VROWS   (BATCH * NVIEW)        // 81920
#define NPOOLCTA 32
#define NVIEWCTA 640
#define NCTA     (NPOOLCTA + NVIEWCTA) // 672

#define FNEW_OFF   0
#define FNEW_CNT   (BATCH * SEL * CDIM)
#define SCORE_OFF  FNEW_CNT
#define SCORE_CNT  (BATCH * NVIEW * NCLS)
#define VNEW_OFF   (SCORE_OFF + SCORE_CNT)

// ============================ mma.sync GEMM config =========================
// fp16 m16n8k16, 2-way split, 3 passes. Scaling: X*16, W*256 -> /4096.
#define BMT       128
#define KCHUNK    32
#define NCHUNKS   (CDIM / KCHUNK)      // 16
#define A_PAD     40
#define XSCALE    16.0f
#define WSCALE    256.0f
#define INVSCALE  (1.0f / 4096.0f)

// smem byte offsets (mainloop double-buffer, region < 106496)
#define OFF_A0    0
#define A_STAGE   (BMT * A_PAD * 4)    // 20480
#define OFF_A1    A_STAGE
#define OFF_B0    (2 * A_STAGE)        // 40960
#define B_STAGE   32768
#define OFF_B1    (OFF_B0 + B_STAGE)   // 73728  (+B_STAGE = 106496)
// epilogue: H fp32 [128][264]; W2 fp16 quads staged above it (disjoint from mainloop)
#define H_STRIDE  264
#define OFF_H     0
#define OFF_W2Q   (BMT * H_STRIDE * 4)             // 135168
#define W2Q_BYTES (16 * NCLS * 4 * 16)             // 40960
#define SMEM_BYTES (OFF_W2Q + W2Q_BYTES)           // 176128

// ============================ device scratch ===============================
__device__ float    g_pooled[BATCH * CDIM];
__device__ int      g_pred[BATCH];
// W1^T fp16 hi/lo quads: [ks16(32)][n(256)][kk(4)] x 16B; {b0hi,b1hi,b0lo,b1lo}
__device__ uint32_t g_w1p[32 * 256 * 4 * 4];   // 512 KB
// W2 fp16 hi/lo quads (same scheme, k-dim = HID): [ks16(16)][n(40)][kk(4)] x 16B
__device__ uint32_t g_w2p[16 * NCLS * 4 * 4];  // 40 KB

// ============================ helpers ======================================
__device__ __forceinline__ uint32_t smem_u32(const void* p) {
    uint32_t a;
    asm("{ .reg .u64 t; cvta.to.shared.u64 t, %1; cvt.u32.u64 %0, t; }" : "=r"(a) : "l"(p));
    return a;
}
__device__ __forceinline__ void mma_f16(float* d, const uint32_t* a, uint32_t b0, uint32_t b1) {
    asm volatile(
        "mma.sync.aligned.m16n8k16.row.col.f32.f16.f16.f32 "
        "{%0,%1,%2,%3}, {%4,%5,%6,%7}, {%8,%9}, {%0,%1,%2,%3};"
        : "+f"(d[0]), "+f"(d[1]), "+f"(d[2]), "+f"(d[3])
        : "r"(a[0]), "r"(a[1]), "r"(a[2]), "r"(a[3]), "r"(b0), "r"(b1));
}
__device__ __forceinline__ void cpasync16(uint32_t dst, const void* src) {
    asm volatile("cp.async.cg.shared.global [%0], [%1], 16;" :: "r"(dst), "l"(src));
}
#define CP_COMMIT()  asm volatile("cp.async.commit_group;" ::: "memory")
#define CP_WAIT(N)   asm volatile("cp.async.wait_group %0;" :: "n"(N) : "memory")

__device__ __forceinline__ void pack_split(float2 v, uint32_t& hi, uint32_t& lo) {
    float x0 = v.x * XSCALE, x1 = v.y * XSCALE;
    __half h0 = __float2half_rn(x0), h1 = __float2half_rn(x1);
    __half2 hp = __halves2half2(h0, h1);
    hi = *reinterpret_cast<uint32_t*>(&hp);
    float r0 = x0 - __half2float(h0), r1 = x1 - __half2float(h1);
    __half2 lp = __halves2half2(__float2half_rn(r0), __float2half_rn(r1));
    lo = *reinterpret_cast<uint32_t*>(&lp);
}
// split a scaled weight into hi/lo and scatter into a quad array
__device__ __forceinline__ void scatter_w(uint16_t* base, int k, float w) {
    __half hi = __float2half_rn(w);
    float r = w - __half2float(hi);
    __half lo = __float2half_rn(r);
    int kpos = k & 15;
    int kk   = (kpos & 7) >> 1;
    int breg = kpos >> 3;
    int hsel = kpos & 1;
    uint16_t* q = base + kk * 8;
    q[breg * 2 + hsel]     = *reinterpret_cast<uint16_t*>(&hi);
    q[4 + breg * 2 + hsel] = *reinterpret_cast<uint16_t*>(&lo);
}

// ---------------------------------------------------------------------------
// Kernel P: split W1*256 and W2*256 into fp16 hi/lo quads (merged)
// ---------------------------------------------------------------------------
#define W1ELEMS (CDIM * HID)           // 131072
#define W2ELEMS (HID * NCLS)           // 10240
__global__ void prep_w_kernel(const float* __restrict__ W1, const float* __restrict__ W2) {
    int i = blockIdx.x * blockDim.x + threadIdx.x;
    if (i < W1ELEMS) {
        int k = i >> 8;                // 0..511
        int n = i & 255;
        int ks = k >> 4;
        uint16_t* base = reinterpret_cast<uint16_t*>(g_w1p) + (size_t)(ks * 256 + n) * 32;
        scatter_w(base, k, W1[i] * WSCALE);
    } else if (i < W1ELEMS + W2ELEMS) {
        int j = i - W1ELEMS;           // over 256*40, row-major [k][n]
        int k = j / NCLS;
        int n = j - k * NCLS;
        int ks = k >> 4;
        uint16_t* base = reinterpret_cast<uint16_t*>(g_w2p) + (size_t)(ks * NCLS + n) * 32;
        scatter_w(base, k, W2[j] * WSCALE);
    }
}

// ---------------------------------------------------------------------------
// Kernel B: 3-pass fp16 mma.sync for BOTH GEMMs, fused pooling.
// ---------------------------------------------------------------------------
__global__ __launch_bounds__(256, 1)
void mlp_mma_kernel(const float* __restrict__ F0,
                    const float* __restrict__ bias1,
                    const float* __restrict__ bias2,
                    float* __restrict__ score_out) {
    extern __shared__ char smem[];
    const uint32_t sb = smem_u32(smem);
    const int t   = threadIdx.x;
    const int wid = t >> 5;
    const int l   = t & 31;
    const int wr  = wid >> 1;
    const int wc  = wid & 1;

    const bool pooled = (blockIdx.x < NPOOLCTA);
    const float* Xbase;
    int blockRow = 0;

    // ---- stage W2 quads early (disjoint smem region; hides under mainloop) ----
    {
        const uint4* src = reinterpret_cast<const uint4*>(g_w2p);
        uint4* dst = reinterpret_cast<uint4*>(smem + OFF_W2Q);
        for (int idx = t; idx < W2Q_BYTES / 16; idx += 256)
            dst[idx] = src[idx];
    }

    if (pooled) {
        // phase 0: pool this CTA's 128 batches (self-produced -> race-free)
        const int b0 = blockIdx.x * BMT;
        float4* dstP = reinterpret_cast<float4*>(g_pooled) + (size_t)b0 * 128;
        const float4* srcP = reinterpret_cast<const float4*>(F0) + (size_t)b0 * (NVIEW * 128);
        const float inv = 1.0f / 20.0f;
        for (int i = t; i < BMT * 128; i += 256) {
            int bb = i >> 7, c4 = i & 127;
            const float4* p = srcP + (size_t)bb * (NVIEW * 128) + c4;
            float4 s = p[0];
#pragma unroll
            for (int n = 1; n < NVIEW; n++) {
                float4 q = p[n * 128];
                s.x += q.x; s.y += q.y; s.z += q.z; s.w += q.w;
            }
            s.x *= inv; s.y *= inv; s.z *= inv; s.w *= inv;
            dstP[i] = s;
        }
        __syncthreads();
        Xbase = g_pooled + (size_t)b0 * CDIM;
    } else {
        blockRow = (blockIdx.x - NPOOLCTA) * BMT;
        Xbase = F0 + (size_t)blockRow * CDIM;
    }

    // ---- GEMM1 accumulators ----
    float acc[2][16][4];
#pragma unroll
    for (int nt = 0; nt < 16; nt++)
#pragma unroll
        for (int mt = 0; mt < 2; mt++) {
            acc[mt][nt][0] = 0.f; acc[mt][nt][1] = 0.f;
            acc[mt][nt][2] = 0.f; acc[mt][nt][3] = 0.f;
        }

    auto load_chunk = [&](int stage, int c) {
        uint32_t dA = sb + (stage ? OFF_A1 : OFF_A0);
        uint32_t dB = sb + (stage ? OFF_B1 : OFF_B0);
#pragma unroll
        for (int j = 0; j < 4; j++) {
            int o = t + j * 256;
            int row = o >> 3, seg = o & 7;
            cpasync16(dA + row * (A_PAD * 4) + seg * 16,
                      (const char*)Xbase + (size_t)row * (CDIM * 4) + c * (KCHUNK * 4) + seg * 16);
        }
        const char* srcB = (const char*)g_w1p + (size_t)c * B_STAGE;
#pragma unroll
        for (int j = 0; j < 8; j++) {
            int off = (t + j * 256) * 16;
            cpasync16(dB + off, srcB + off);
        }
    };

    load_chunk(0, 0);
    CP_COMMIT();

#pragma unroll 1
    for (int c = 0; c < NCHUNKS; c++) {
        if (c < NCHUNKS - 1) {
            load_chunk((c + 1) & 1, c + 1);
            CP_COMMIT();
            CP_WAIT(1);
        } else {
            CP_WAIT(0);
        }
        __syncthreads();

        const float* Asm = (const float*)(smem + ((c & 1) ? OFF_A1 : OFF_A0));
        const char*  Bsm = smem + ((c & 1) ? OFF_B1 : OFF_B0);

#pragma unroll
        for (int s = 0; s < 2; s++) {
            uint32_t aHi[2][4], aLo[2][4];
#pragma unroll
            for (int mt = 0; mt < 2; mt++) {
                int r0 = wr * 32 + mt * 16 + (l >> 2);
                int c0 = s * 16 + 2 * (l & 3);
                const float* Ar  = Asm + r0 * A_PAD;
                const float* Ar8 = Asm + (r0 + 8) * A_PAD;
                pack_split(*(const float2*)&Ar[c0],      aHi[mt][0], aLo[mt][0]);
                pack_split(*(const float2*)&Ar8[c0],     aHi[mt][1], aLo[mt][1]);
                pack_split(*(const float2*)&Ar[c0 + 8],  aHi[mt][2], aLo[mt][2]);
                pack_split(*(const float2*)&Ar8[c0 + 8], aHi[mt][3], aLo[mt][3]);
            }
#pragma unroll
            for (int nt = 0; nt < 16; nt++) {
                uint4 q = *(const uint4*)(Bsm + s * 16384 + (wc * 512 + nt * 32 + l) * 16);
#pragma unroll
                for (int mt = 0; mt < 2; mt++) {
                    mma_f16(acc[mt][nt], aHi[mt], q.z, q.w);   // hiA * loB
                    mma_f16(acc[mt][nt], aLo[mt], q.x, q.y);   // loA * hiB
                    mma_f16(acc[mt][nt], aHi[mt], q.x, q.y);   // hiA * hiB
                }
            }
        }
        __syncthreads();
    }

    // ---- epilogue: unscale + bias + LeakyReLU -> H smem (stride 264) ----
    float* Hf = (float*)(smem + OFF_H);
#pragma unroll
    for (int mt = 0; mt < 2; mt++) {
        int r0 = wr * 32 + mt * 16 + (l >> 2);
#pragma unroll
        for (int nt = 0; nt < 16; nt++) {
            int n0 = wc * 128 + nt * 8 + 2 * (l & 3);
            float b0v = bias1[n0], b1v = bias1[n0 + 1];
            float2 p; float v;
            v = acc[mt][nt][0] * INVSCALE + b0v; p.x = v > 0.f ? v : 0.2f * v;
            v = acc[mt][nt][1] * INVSCALE + b1v; p.y = v > 0.f ? v : 0.2f * v;
            *(float2*)&Hf[r0 * H_STRIDE + n0] = p;
            v = acc[mt][nt][2] * INVSCALE + b0v; p.x = v > 0.f ? v : 0.2f * v;
            v = acc[mt][nt][3] * INVSCALE + b1v; p.y = v > 0.f ? v : 0.2f * v;
            *(float2*)&Hf[(r0 + 8) * H_STRIDE + n0] = p;
        }
    }
    __syncthreads();

    // ---- GEMM2 via fp16 MMA (3 passes): 128x40 = H @ W2 ----
    // Warp wid owns m-tile rows [wid*16, wid*16+16). 5 n-tiles of 8.
    const uint32_t* W2q = (const uint32_t*)(smem + OFF_W2Q);
    float acc2[5][4];
#pragma unroll
    for (int nt = 0; nt < 5; nt++) {
        acc2[nt][0] = 0.f; acc2[nt][1] = 0.f; acc2[nt][2] = 0.f; acc2[nt][3] = 0.f;
    }
    const int rbase = wid * 16 + (l >> 2);
#pragma unroll 4
    for (int ks = 0; ks < 16; ks++) {
        int c0 = ks * 16 + 2 * (l & 3);
        const float* Hr  = Hf + rbase * H_STRIDE;
        const float* Hr8 = Hf + (rbase + 8) * H_STRIDE;
        uint32_t aHi[4], aLo[4];
        pack_split(*(const float2*)&Hr[c0],      aHi[0], aLo[0]);
        pack_split(*(const float2*)&Hr8[c0],     aHi[1], aLo[1]);
        pack_split(*(const float2*)&Hr[c0 + 8],  aHi[2], aLo[2]);
        pack_split(*(const float2*)&Hr8[c0 + 8], aHi[3], aLo[3]);
#pragma unroll
        for (int nt = 0; nt < 5; nt++) {
            uint4 q = *(const uint4*)(W2q + ((size_t)(ks * NCLS + nt * 8 + (l >> 2)) * 4 + (l & 3)) * 4);
            mma_f16(acc2[nt], aHi, q.z, q.w);   // hiH * loW
            mma_f16(acc2[nt], aLo, q.x, q.y);   // loH * hiW
            mma_f16(acc2[nt], aHi, q.x, q.y);   // hiH * hiW
        }
    }
    __syncthreads();   // all H reads done -> reuse region for score tile

    // stage score tile [128][40] flat (unscale + bias2)
#pragma unroll
    for (int nt = 0; nt < 5; nt++) {
        int col = nt * 8 + (l & 3) * 2;
        float b0v = bias2[col], b1v = bias2[col + 1];
        Hf[rbase * NCLS + col]           = acc2[nt][0] * INVSCALE + b0v;
        Hf[rbase * NCLS + col + 1]       = acc2[nt][1] * INVSCALE + b1v;
        Hf[(rbase + 8) * NCLS + col]     = acc2[nt][2] * INVSCALE + b0v;
        Hf[(rbase + 8) * NCLS + col + 1] = acc2[nt][3] * INVSCALE + b1v;
    }
    __syncthreads();

    if (!pooled) {
        float* dst = score_out + (size_t)blockRow * NCLS;
        for (int idx = t; idx < BMT * NCLS; idx += 256)
            dst[idx] = Hf[idx];
    } else if (t < BMT) {
        const float* row = &Hf[t * NCLS];
        float best = row[0]; int bi = 0;
#pragma unroll
        for (int i = 1; i < NCLS; i++)
            if (row[i] > best) { best = row[i]; bi = i; }   // first max (jnp.argmax)
        g_pred[blockIdx.x * BMT + t] = bi;
    }
}

// ---------------------------------------------------------------------------
// Kernel C: 8 batches/block; warp-topk + wide gather. [R7/R8-proven]
// ---------------------------------------------------------------------------
__global__ __launch_bounds__(256)
void select_kernel(const float* __restrict__ F0,
                   const float* __restrict__ V0,
                   const float* __restrict__ score,
                   float* __restrict__ Fnew,
                   float* __restrict__ Vnew) {
    const int t = threadIdx.x;
    const int w = t >> 5;
    const int lane = t & 31;
    const int b = blockIdx.x * 8 + w;
    __shared__ int sidx[8][SEL];

    {
        int pred = g_pred[b];
        float v = (lane < NVIEW) ? score[((size_t)b * NVIEW + lane) * NCLS + pred] : -FLT_MAX;
        int myn = lane;
#pragma unroll
        for (int sstep = 0; sstep < SEL; sstep++) {
            float bv = v; int bi = myn;
#pragma unroll
            for (int off = 16; off > 0; off >>= 1) {
                float ov = __shfl_down_sync(0xffffffffu, bv, off);
                int   oi = __shfl_down_sync(0xffffffffu, bi, off);
                if (ov > bv || (ov == bv && oi < bi)) { bv = ov; bi = oi; }
            }
            bi = __shfl_sync(0xffffffffu, bi, 0);
            if (lane == 0) sidx[w][sstep] = bi;
            if (myn == bi) v = -FLT_MAX;
        }
    }
    __syncthreads();

    const float4* Fsrc = reinterpret_cast<const float4*>(F0);
    float4* Fdst = reinterpret_cast<float4*>(Fnew);
#pragma unroll
    for (int j = 0; j < 32; j++) {
        int i = t + j * 256;
        int bl = i >> 10, srow = (i >> 7) & 7, c = i & 127;
        int bb = blockIdx.x * 8 + bl;
        Fdst[((size_t)bb * SEL + srow) * 128 + c] =
            Fsrc[((size_t)bb * NVIEW + sidx[bl][srow]) * 128 + c];
    }
    if (t < 8 * SEL * 3) {
        int bl = t / (SEL * 3), r = t % (SEL * 3);
        int srow = r / 3, cmp = r - srow * 3;
        int bb = blockIdx.x * 8 + bl;
        Vnew[(size_t)bb * (SEL * 3) + r] = V0[(size_t)bb * (NVIEW * 3) + sidx[bl][srow] * 3 + cmp];
    }
}

// ---------------------------------------------------------------------------
extern "C" void kernel_launch(void* const* d_in, const int* in_sizes, int n_in,
                              void* d_out, int out_size) {
    (void)in_sizes; (void)n_in; (void)out_size;
    const float* F0 = (const float*)d_in[0];
    const float* V0 = (const float*)d_in[1];
    const float* W1 = (const float*)d_in[2];
    const float* b1 = (const float*)d_in[3];
    const float* W2 = (const float*)d_in[4];
    const float* b2 = (const float*)d_in[5];
    float* out   = (float*)d_out;
    float* Fnew  = out + FNEW_OFF;
    float* score = out + SCORE_OFF;
    float* Vnew  = out + VNEW_OFF;

    cudaFuncSetAttribute(mlp_mma_kernel, cudaFuncAttributeMaxDynamicSharedMemorySize, SMEM_BYTES);

    prep_w_kernel<<<(W1ELEMS + W2ELEMS + 255) / 256, 256>>>(W1, W2);
    mlp_mma_kernel<<<NCTA, 256, SMEM_BYTES>>>(F0, b1, b2, score);
    select_kernel<<<BATCH / 8, 256>>>(F0, V0, score, Fnew, Vnew);
}